// round 1
// baseline (speedup 1.0000x reference)
#include <cuda_runtime.h>

// Problem constants (fixed by the reference):
//   q,k,v: (H=8, B=256, L=128, D=64) fp32
//   pos_bias: (H, 1, L, L) fp32
//   out = softmax(qK^T/8 + bias) V ; also emit attn probabilities.
//   d_out = [ out (H,B,L,D) | attn (H,B,L,L) ]  (reference tuple order)

#define HH   8
#define BSZ  256
#define LL   128
#define DD   64
#define KS   68    // smem row stride for K/V tile (padded)
#define PS   132   // smem row stride for P/S tile (padded, float4-aligned)

static __device__ __forceinline__ float4 ldg4(const float4* p) { return *p; }

__global__ __launch_bounds__(256, 2)
void attn_fused_kernel(const float* __restrict__ qg_,
                       const float* __restrict__ kg_,
                       const float* __restrict__ vg_,
                       const float* __restrict__ biasg,
                       float* __restrict__ outg,
                       float* __restrict__ attng)
{
    extern __shared__ float sm[];
    float* sK = sm;                 // LL * KS floats  (K tile, later V tile)
    float* sP = sm + LL * KS;       // LL * PS floats  (Q stage, then S/P tile)

    const int b = blockIdx.x;
    const int h = blockIdx.y;
    const int t = threadIdx.x;

    const size_t qkv_base  = (((size_t)h * BSZ + b) * LL) * DD;  // in floats
    const size_t attn_base = (((size_t)h * BSZ + b) * LL) * LL;
    const float* qg = qg_ + qkv_base;
    const float* kg = kg_ + qkv_base;
    const float* vg = vg_ + qkv_base;
    const float* bg = biasg + (size_t)h * LL * LL;

    // ---- Phase 0: cooperative coalesced load  K -> sK,  Q -> sP (staging) ----
    // L*D = 8192 floats = 2048 float4, 256 threads -> 8 iters each.
    #pragma unroll
    for (int it = 0; it < (LL * DD / 4) / 256; ++it) {
        int idx = t + it * 256;
        int row = idx >> 4;            // D/4 = 16 float4 per row
        int c4  = idx & 15;
        float4 kk = ldg4((const float4*)kg + idx);
        float4 qq = ldg4((const float4*)qg + idx);
        *(float4*)&sK[row * KS + c4 * 4] = kk;
        *(float4*)&sP[row * PS + c4 * 4] = qq;
    }
    __syncthreads();

    const int i  = t >> 1;   // query row owned by this thread (2 threads/row)
    const int hf = t & 1;    // which half (keys for phase 1, dims for phase 2)

    // ---- pull q row into registers from the staged copy ----
    float qr[DD];
    #pragma unroll
    for (int c4 = 0; c4 < DD / 4; ++c4) {
        float4 f = *(const float4*)&sP[i * PS + c4 * 4];
        qr[c4 * 4 + 0] = f.x; qr[c4 * 4 + 1] = f.y;
        qr[c4 * 4 + 2] = f.z; qr[c4 * 4 + 3] = f.w;
    }
    __syncthreads();   // all threads captured q; sP may now be overwritten

    // ---- Phase 1: S[i][jj] = (q_i . k_jj)/8 + bias[i][jj],  jj in [hf*64, hf*64+64) ----
    const float* brow = bg + (size_t)i * LL + hf * 64;
    float* srow = &sP[i * PS + hf * 64];
    #pragma unroll 1
    for (int jg = 0; jg < 16; ++jg) {          // 4 keys per group
        float4 b4 = ldg4((const float4*)brow + jg);
        float sv[4];
        #pragma unroll
        for (int u = 0; u < 4; ++u) {
            const int jj = hf * 64 + jg * 4 + u;
            const float* krow = &sK[jj * KS];
            float a0 = 0.f, a1 = 0.f, a2 = 0.f, a3 = 0.f;
            #pragma unroll
            for (int c4 = 0; c4 < DD / 4; ++c4) {
                float4 kk = *(const float4*)&krow[c4 * 4];
                a0 = fmaf(qr[c4 * 4 + 0], kk.x, a0);
                a1 = fmaf(qr[c4 * 4 + 1], kk.y, a1);
                a2 = fmaf(qr[c4 * 4 + 2], kk.z, a2);
                a3 = fmaf(qr[c4 * 4 + 3], kk.w, a3);
            }
            sv[u] = (a0 + a1) + (a2 + a3);
        }
        srow[jg * 4 + 0] = fmaf(sv[0], 0.125f, b4.x);
        srow[jg * 4 + 1] = fmaf(sv[1], 0.125f, b4.y);
        srow[jg * 4 + 2] = fmaf(sv[2], 0.125f, b4.z);
        srow[jg * 4 + 3] = fmaf(sv[3], 0.125f, b4.w);
    }
    __syncthreads();

    // ---- Softmax over row i (2 threads per row, combine via shfl with lane^1) ----
    {
        float m = -1e30f;
        #pragma unroll
        for (int j = 0; j < 64; ++j) m = fmaxf(m, srow[j]);
        m = fmaxf(m, __shfl_xor_sync(0xffffffffu, m, 1));
        float s = 0.f;
        #pragma unroll
        for (int j = 0; j < 64; ++j) {
            float e = __expf(srow[j] - m);
            srow[j] = e;
            s += e;
        }
        s += __shfl_xor_sync(0xffffffffu, s, 1);
        float r = 1.f / s;
        #pragma unroll
        for (int j = 0; j < 64; ++j) srow[j] *= r;
    }
    __syncthreads();

    // ---- Load V into sK region; coalesced copy P -> attn gmem ----
    #pragma unroll
    for (int it = 0; it < (LL * DD / 4) / 256; ++it) {
        int idx = t + it * 256;
        int row = idx >> 4;
        int c4  = idx & 15;
        *(float4*)&sK[row * KS + c4 * 4] = ldg4((const float4*)vg + idx);
    }
    {
        float* ag = attng + attn_base;
        #pragma unroll
        for (int it = 0; it < (LL * LL / 4) / 256; ++it) {   // 16 iters
            int idx = t + it * 256;
            int row = idx >> 5;        // L/4 = 32 float4 per row
            int c4  = idx & 31;
            ((float4*)ag)[idx] = *(const float4*)&sP[row * PS + c4 * 4];
        }
    }
    __syncthreads();

    // ---- Phase 2: out[i][d] = sum_j P[i][j] * V[j][d], d in [hf*32, hf*32+32) ----
    float acc[32];
    #pragma unroll
    for (int d = 0; d < 32; ++d) acc[d] = 0.f;
    const float* prow = &sP[i * PS];
    #pragma unroll 4
    for (int j = 0; j < LL; ++j) {
        float p = prow[j];
        const float* vrow = &sK[j * KS + hf * 32];
        #pragma unroll
        for (int c4 = 0; c4 < 8; ++c4) {
            float4 vv = *(const float4*)&vrow[c4 * 4];
            acc[c4 * 4 + 0] = fmaf(p, vv.x, acc[c4 * 4 + 0]);
            acc[c4 * 4 + 1] = fmaf(p, vv.y, acc[c4 * 4 + 1]);
            acc[c4 * 4 + 2] = fmaf(p, vv.z, acc[c4 * 4 + 2]);
            acc[c4 * 4 + 3] = fmaf(p, vv.w, acc[c4 * 4 + 3]);
        }
    }
    float* og = outg + qkv_base + (size_t)i * DD + hf * 32;
    #pragma unroll
    for (int c4 = 0; c4 < 8; ++c4) {
        float4 o;
        o.x = acc[c4 * 4 + 0]; o.y = acc[c4 * 4 + 1];
        o.z = acc[c4 * 4 + 2]; o.w = acc[c4 * 4 + 3];
        ((float4*)og)[c4] = o;
    }
}

extern "C" void kernel_launch(void* const* d_in, const int* in_sizes, int n_in,
                              void* d_out, int out_size)
{
    const float* q    = (const float*)d_in[0];
    const float* k    = (const float*)d_in[1];
    const float* v    = (const float*)d_in[2];
    const float* bias = (const float*)d_in[3];

    float* out  = (float*)d_out;
    float* attn = out + (size_t)HH * BSZ * LL * DD;   // tuple order: (out, attn)

    const size_t smem = (size_t)(LL * KS + LL * PS) * sizeof(float);  // 102400 B
    cudaFuncSetAttribute(attn_fused_kernel,
                         cudaFuncAttributeMaxDynamicSharedMemorySize, (int)smem);

    dim3 grid(BSZ, HH);
    attn_fused_kernel<<<grid, 256, smem>>>(q, k, v, bias, out, attn);
}

// round 2
// speedup vs baseline: 1.9458x; 1.9458x over previous
#include <cuda_runtime.h>

// q,k,v: (H=8, B=256, L=128, D=64) fp32 ; pos_bias: (H,1,L,L)
// d_out = [ out (H,B,L,D) | attn (H,B,L,L) ]
#define HH   8
#define BSZ  256
#define LL   128
#define DD   64

// packed fp32x2 FMA: d = a*b + d (elementwise on the two lanes)
#define FMA2(d, a, b) \
    asm("fma.rn.f32x2 %0, %1, %2, %0;" : "+l"(d) : "l"(a), "l"(b))

static __device__ __forceinline__ float lo32(unsigned long long v) {
    return __uint_as_float((unsigned)(v & 0xffffffffull));
}
static __device__ __forceinline__ float hi32(unsigned long long v) {
    return __uint_as_float((unsigned)(v >> 32));
}

__global__ __launch_bounds__(512, 1)
void attn_v2_kernel(const float* __restrict__ qg_,
                    const float* __restrict__ kg_,
                    const float* __restrict__ vg_,
                    const float* __restrict__ biasg,
                    float* __restrict__ outg,
                    float* __restrict__ attng)
{
    extern __shared__ float sm[];
    float* sQ  = sm;            // 128 x 64            (8192 floats)
    float* sK2 = sm + 8192;     // 32 d2-rows x 256    (K pairs: (j, d-pair))
    float* sV2 = sm + 16384;    // 64 j2-rows x 128    (V pairs: (d, j-pair))
    float* sP  = sm + 24576;    // 128 x 128 probs

    const int b = blockIdx.x;
    const int h = blockIdx.y;
    const int t = threadIdx.x;

    const size_t base  = (((size_t)h * BSZ + b) * LL) * DD;
    const size_t abase = (((size_t)h * BSZ + b) * LL) * LL;
    const float4* q4 = (const float4*)(qg_ + base);
    const float4* k4 = (const float4*)(kg_ + base);
    const float4* v4 = (const float4*)(vg_ + base);
    const float*  bg = biasg + (size_t)h * LL * LL;
    float*        ag = attng + abase;
    float*        og = outg + base;

    // ---- Stage Q (linear copy) ----
    #pragma unroll
    for (int it = 0; it < 4; ++it)
        ((float4*)sQ)[t + it * 512] = q4[t + it * 512];

    // ---- Stage K as d-pairs, transposed: sK2[d2][j] = (K[j][2*d2], K[j][2*d2+1]) ----
    {
        const int db = t & 15;       // d-block (4 dims)
        const int jb = t >> 4;       // j-block (4 keys), 0..31
        float4 r0 = k4[(jb * 4 + 0) * 16 + db];
        float4 r1 = k4[(jb * 4 + 1) * 16 + db];
        float4 r2 = k4[(jb * 4 + 2) * 16 + db];
        float4 r3 = k4[(jb * 4 + 3) * 16 + db];
        float* w0 = &sK2[(2 * db + 0) * 256 + jb * 8];
        float* w1 = &sK2[(2 * db + 1) * 256 + jb * 8];
        ((float4*)w0)[0] = make_float4(r0.x, r0.y, r1.x, r1.y);
        ((float4*)w0)[1] = make_float4(r2.x, r2.y, r3.x, r3.y);
        ((float4*)w1)[0] = make_float4(r0.z, r0.w, r1.z, r1.w);
        ((float4*)w1)[1] = make_float4(r2.z, r2.w, r3.z, r3.w);
    }

    // ---- Stage V as j-pairs: sV2[j2][d] = (V[2*j2][d], V[2*j2+1][d]) ----
    #pragma unroll
    for (int it = 0; it < 2; ++it) {
        int idx = t + it * 512;
        int db = idx & 15;           // 4 dims
        int j2 = idx >> 4;           // 0..63
        float4 a  = v4[(2 * j2 + 0) * 16 + db];
        float4 bb = v4[(2 * j2 + 1) * 16 + db];
        float* w = &sV2[j2 * 128 + db * 8];
        ((float4*)w)[0] = make_float4(a.x, bb.x, a.y, bb.y);
        ((float4*)w)[1] = make_float4(a.z, bb.z, a.w, bb.w);
    }
    __syncthreads();

    // =================== Phase 1: S = Q K^T /8 + bias, softmax ===================
    // warp w owns rows i0..i0+7 entirely; lane tx owns cols {tx, tx+32, tx+64, tx+96}
    const int tx = t & 31;
    const int ty = t >> 5;
    const int i0 = ty * 8;

    unsigned long long acc[8][4];
    #pragma unroll
    for (int r = 0; r < 8; ++r)
        #pragma unroll
        for (int c = 0; c < 4; ++c) acc[r][c] = 0ull;

    #pragma unroll 4
    for (int d2 = 0; d2 < 32; ++d2) {
        const float* krow = &sK2[d2 * 256 + 2 * tx];
        unsigned long long kp0 = *(const unsigned long long*)&krow[0];
        unsigned long long kp1 = *(const unsigned long long*)&krow[64];
        unsigned long long kp2 = *(const unsigned long long*)&krow[128];
        unsigned long long kp3 = *(const unsigned long long*)&krow[192];
        #pragma unroll
        for (int r = 0; r < 8; ++r) {
            unsigned long long qp =
                *(const unsigned long long*)&sQ[(i0 + r) * 64 + 2 * d2];
            FMA2(acc[r][0], qp, kp0);
            FMA2(acc[r][1], qp, kp1);
            FMA2(acc[r][2], qp, kp2);
            FMA2(acc[r][3], qp, kp3);
        }
    }

    // softmax (entirely within the warp), write attn + sP
    #pragma unroll
    for (int r = 0; r < 8; ++r) {
        const int i = i0 + r;
        float s[4];
        #pragma unroll
        for (int c = 0; c < 4; ++c) {
            float dot = lo32(acc[r][c]) + hi32(acc[r][c]);
            s[c] = fmaf(dot, 0.125f, __ldg(&bg[i * LL + tx + 32 * c]));
        }
        float m = fmaxf(fmaxf(s[0], s[1]), fmaxf(s[2], s[3]));
        #pragma unroll
        for (int off = 16; off >= 1; off >>= 1)
            m = fmaxf(m, __shfl_xor_sync(0xffffffffu, m, off));
        float e[4], sum = 0.f;
        #pragma unroll
        for (int c = 0; c < 4; ++c) { e[c] = __expf(s[c] - m); sum += e[c]; }
        #pragma unroll
        for (int off = 16; off >= 1; off >>= 1)
            sum += __shfl_xor_sync(0xffffffffu, sum, off);
        float inv = 1.0f / sum;
        #pragma unroll
        for (int c = 0; c < 4; ++c) {
            float p = e[c] * inv;
            ag[i * LL + tx + 32 * c] = p;
            sP[i * LL + tx + 32 * c] = p;
        }
    }
    __syncthreads();

    // =================== Phase 2: O = P V ===================
    // lane tx2 owns dims {tx2, tx2+16, tx2+32, tx2+48}; ty2 owns rows i0b..i0b+3
    const int tx2 = t & 15;
    const int ty2 = t >> 4;
    const int i0b = ty2 * 4;

    unsigned long long acc2[4][4];
    #pragma unroll
    for (int r = 0; r < 4; ++r)
        #pragma unroll
        for (int u = 0; u < 4; ++u) acc2[r][u] = 0ull;

    #pragma unroll 4
    for (int j2 = 0; j2 < 64; ++j2) {
        const float* vrow = &sV2[j2 * 128 + 2 * tx2];
        unsigned long long vp0 = *(const unsigned long long*)&vrow[0];
        unsigned long long vp1 = *(const unsigned long long*)&vrow[32];
        unsigned long long vp2 = *(const unsigned long long*)&vrow[64];
        unsigned long long vp3 = *(const unsigned long long*)&vrow[96];
        #pragma unroll
        for (int r = 0; r < 4; ++r) {
            unsigned long long pp =
                *(const unsigned long long*)&sP[(i0b + r) * LL + 2 * j2];
            FMA2(acc2[r][0], pp, vp0);
            FMA2(acc2[r][1], pp, vp1);
            FMA2(acc2[r][2], pp, vp2);
            FMA2(acc2[r][3], pp, vp3);
        }
    }

    #pragma unroll
    for (int r = 0; r < 4; ++r)
        #pragma unroll
        for (int u = 0; u < 4; ++u)
            og[(i0b + r) * DD + tx2 + 16 * u] =
                lo32(acc2[r][u]) + hi32(acc2[r][u]);
}

extern "C" void kernel_launch(void* const* d_in, const int* in_sizes, int n_in,
                              void* d_out, int out_size)
{
    const float* q    = (const float*)d_in[0];
    const float* k    = (const float*)d_in[1];
    const float* v    = (const float*)d_in[2];
    const float* bias = (const float*)d_in[3];

    float* out  = (float*)d_out;
    float* attn = out + (size_t)HH * BSZ * LL * DD;

    const size_t smem = 40960 * sizeof(float);   // 160 KB
    cudaFuncSetAttribute(attn_v2_kernel,
                         cudaFuncAttributeMaxDynamicSharedMemorySize, (int)smem);

    dim3 grid(BSZ, HH);
    attn_v2_kernel<<<grid, 512, smem>>>(q, k, v, bias, out, attn);
}

// round 4
// speedup vs baseline: 3.9427x; 2.0262x over previous
#include <cuda_runtime.h>
#include <cuda_bf16.h>
#include <cstdint>

// q,k,v: (H=8, B=256, L=128, D=64) fp32 ; pos_bias: (H,1,L,L)
// d_out = [ out (H,B,L,D) | attn (H,B,L,L) ]
#define HH 8
#define BSZ 256
#define LL 128
#define DD 64

#define KSTRIDE 36   // u32 stride per K row (bank map (4g+t)%32: conflict-free)
#define VSTRIDE 68   // u32 stride per Vt row (same property)

// pack two floats -> bf16x2 (lo -> bits[15:0], hi -> bits[31:16])
static __device__ __forceinline__ uint32_t packbf(float lo, float hi) {
    uint32_t r;
    asm("cvt.rn.bf16x2.f32 %0, %1, %2;" : "=r"(r) : "f"(hi), "f"(lo));
    return r;
}
static __device__ __forceinline__ float bf16rt(float x) {
    return __bfloat162float(__float2bfloat16_rn(x));
}

// D += A * B  (m16n8k16, bf16 in, f32 accum)
static __device__ __forceinline__ void mma16816(float* d, const uint32_t* a,
                                                uint32_t b0, uint32_t b1) {
    asm volatile(
        "mma.sync.aligned.m16n8k16.row.col.f32.bf16.bf16.f32 "
        "{%0,%1,%2,%3}, {%4,%5,%6,%7}, {%8,%9}, {%0,%1,%2,%3};"
        : "+f"(d[0]), "+f"(d[1]), "+f"(d[2]), "+f"(d[3])
        : "r"(a[0]), "r"(a[1]), "r"(a[2]), "r"(a[3]), "r"(b0), "r"(b1));
}

static __device__ __forceinline__ void split4(float4 x, uint2& h, uint2& l) {
    float hx = bf16rt(x.x), hy = bf16rt(x.y), hz = bf16rt(x.z), hw = bf16rt(x.w);
    h = make_uint2(packbf(hx, hy), packbf(hz, hw));
    l = make_uint2(packbf(x.x - hx, x.y - hy), packbf(x.z - hz, x.w - hw));
}

__global__ __launch_bounds__(256, 2)
void attn_hmma_kernel(const float* __restrict__ qg_,
                      const float* __restrict__ kg_,
                      const float* __restrict__ vg_,
                      const float* __restrict__ biasg,
                      float* __restrict__ outg,
                      float* __restrict__ attng)
{
    extern __shared__ uint32_t smu[];
    uint32_t* sKh = smu;                          // 128*36
    uint32_t* sKl = smu + 128 * KSTRIDE;          // 128*36
    uint32_t* sVh = smu + 2 * 128 * KSTRIDE;      // 64*68  (V transposed)
    uint32_t* sVl = sVh + 64 * VSTRIDE;           // 64*68   -> 71680 B total

    const int t = threadIdx.x;
    const int b = blockIdx.x;
    const int h = blockIdx.y;

    const size_t base  = (((size_t)h * BSZ + b) * LL) * DD;
    const size_t abase = (((size_t)h * BSZ + b) * LL) * LL;
    const float*  qg = qg_ + base;
    const float4* k4 = (const float4*)(kg_ + base);
    const float4* v4 = (const float4*)(vg_ + base);
    const float*  bg = biasg + (size_t)h * LL * LL;
    float*        ag = attng + abase;
    float*        og = outg + base;

    // ---- Stage K hi/lo (row-major) ----
    #pragma unroll
    for (int it = 0; it < 8; ++it) {
        int idx = t + it * 256;
        int row = idx >> 4, cg = idx & 15;
        uint2 hh, ll;
        split4(k4[idx], hh, ll);
        *(uint2*)&sKh[row * KSTRIDE + cg * 2] = hh;
        *(uint2*)&sKl[row * KSTRIDE + cg * 2] = ll;
    }
    // ---- Stage V transposed hi/lo: Vt[d][j] ----
    {
        __nv_bfloat16* vh = (__nv_bfloat16*)sVh;
        __nv_bfloat16* vl = (__nv_bfloat16*)sVl;
        #pragma unroll
        for (int it = 0; it < 8; ++it) {
            int idx = t + it * 256;
            int j = idx >> 4, cg = idx & 15;
            float4 x = v4[idx];
            float vv[4] = {x.x, x.y, x.z, x.w};
            #pragma unroll
            for (int u = 0; u < 4; ++u) {
                int d = cg * 4 + u;
                __nv_bfloat16 hb = __float2bfloat16_rn(vv[u]);
                vh[d * (2 * VSTRIDE) + j] = hb;
                vl[d * (2 * VSTRIDE) + j] =
                    __float2bfloat16_rn(vv[u] - __bfloat162float(hb));
            }
        }
    }
    __syncthreads();

    const int w = t >> 5, lane = t & 31;
    const int g = lane >> 2, tq = lane & 3;
    const int i0 = w * 16;
    const int rA = i0 + g, rB = i0 + g + 8;

    // =================== MMA 1: S = (Q K^T), split precision ===================
    float S[16][4];
    #pragma unroll
    for (int nt = 0; nt < 16; ++nt)
        S[nt][0] = S[nt][1] = S[nt][2] = S[nt][3] = 0.f;

    const float* qrA = qg + rA * DD;
    const float* qrB = qg + rB * DD;
    #pragma unroll
    for (int u = 0; u < 4; ++u) {             // k-chunks over d (4 x 16)
        uint32_t qh[4], ql[4];
        {
            float2 x0 = *(const float2*)&qrA[16 * u + 2 * tq];
            float2 x1 = *(const float2*)&qrB[16 * u + 2 * tq];
            float2 x2 = *(const float2*)&qrA[16 * u + 2 * tq + 8];
            float2 x3 = *(const float2*)&qrB[16 * u + 2 * tq + 8];
            float h0 = bf16rt(x0.x), h1 = bf16rt(x0.y);
            qh[0] = packbf(h0, h1); ql[0] = packbf(x0.x - h0, x0.y - h1);
            h0 = bf16rt(x1.x); h1 = bf16rt(x1.y);
            qh[1] = packbf(h0, h1); ql[1] = packbf(x1.x - h0, x1.y - h1);
            h0 = bf16rt(x2.x); h1 = bf16rt(x2.y);
            qh[2] = packbf(h0, h1); ql[2] = packbf(x2.x - h0, x2.y - h1);
            h0 = bf16rt(x3.x); h1 = bf16rt(x3.y);
            qh[3] = packbf(h0, h1); ql[3] = packbf(x3.x - h0, x3.y - h1);
        }
        #pragma unroll
        for (int nt = 0; nt < 16; ++nt) {
            int off = (nt * 8 + g) * KSTRIDE + 8 * u + tq;
            uint32_t bh0 = sKh[off], bh1 = sKh[off + 4];
            uint32_t bl0 = sKl[off], bl1 = sKl[off + 4];
            mma16816(S[nt], qh, bh0, bh1);   // qh*kh
            mma16816(S[nt], qh, bl0, bl1);   // qh*kl
            mma16816(S[nt], ql, bh0, bh1);   // ql*kh
        }
    }

    // =================== softmax (register/warp-local) ===================
    const float* bA = bg + (size_t)rA * LL;
    const float* bB = bg + (size_t)rB * LL;
    float mA = -1e30f, mB = -1e30f;
    #pragma unroll
    for (int nt = 0; nt < 16; ++nt) {
        float2 b0 = __ldg((const float2*)&bA[8 * nt + 2 * tq]);
        float2 b1 = __ldg((const float2*)&bB[8 * nt + 2 * tq]);
        S[nt][0] = fmaf(S[nt][0], 0.125f, b0.x);
        S[nt][1] = fmaf(S[nt][1], 0.125f, b0.y);
        S[nt][2] = fmaf(S[nt][2], 0.125f, b1.x);
        S[nt][3] = fmaf(S[nt][3], 0.125f, b1.y);
        mA = fmaxf(mA, fmaxf(S[nt][0], S[nt][1]));
        mB = fmaxf(mB, fmaxf(S[nt][2], S[nt][3]));
    }
    mA = fmaxf(mA, __shfl_xor_sync(0xffffffffu, mA, 1));
    mA = fmaxf(mA, __shfl_xor_sync(0xffffffffu, mA, 2));
    mB = fmaxf(mB, __shfl_xor_sync(0xffffffffu, mB, 1));
    mB = fmaxf(mB, __shfl_xor_sync(0xffffffffu, mB, 2));

    float sA = 0.f, sB = 0.f;
    #pragma unroll
    for (int nt = 0; nt < 16; ++nt) {
        S[nt][0] = __expf(S[nt][0] - mA); sA += S[nt][0];
        S[nt][1] = __expf(S[nt][1] - mA); sA += S[nt][1];
        S[nt][2] = __expf(S[nt][2] - mB); sB += S[nt][2];
        S[nt][3] = __expf(S[nt][3] - mB); sB += S[nt][3];
    }
    sA += __shfl_xor_sync(0xffffffffu, sA, 1);
    sA += __shfl_xor_sync(0xffffffffu, sA, 2);
    sB += __shfl_xor_sync(0xffffffffu, sB, 1);
    sB += __shfl_xor_sync(0xffffffffu, sB, 2);
    const float iA = 1.f / sA, iB = 1.f / sB;

    float* aA = ag + (size_t)rA * LL;
    float* aB = ag + (size_t)rB * LL;
    #pragma unroll
    for (int nt = 0; nt < 16; ++nt) {
        S[nt][0] *= iA; S[nt][1] *= iA; S[nt][2] *= iB; S[nt][3] *= iB;
        *(float2*)&aA[8 * nt + 2 * tq] = make_float2(S[nt][0], S[nt][1]);
        *(float2*)&aB[8 * nt + 2 * tq] = make_float2(S[nt][2], S[nt][3]);
    }

    // =================== MMA 2: O = P V, split precision ===================
    // A-fragment (P) rebuilt in registers from the S accumulators.
    float O[8][4];
    #pragma unroll
    for (int nt = 0; nt < 8; ++nt)
        O[nt][0] = O[nt][1] = O[nt][2] = O[nt][3] = 0.f;

    #pragma unroll
    for (int u = 0; u < 8; ++u) {             // k-chunks over j (8 x 16)
        uint32_t aH[4], aL[4];
        {
            float p0 = S[2 * u][0], p1 = S[2 * u][1];
            float p2 = S[2 * u][2], p3 = S[2 * u][3];
            float h0 = bf16rt(p0), h1 = bf16rt(p1), h2 = bf16rt(p2), h3 = bf16rt(p3);
            aH[0] = packbf(h0, h1);           aH[1] = packbf(h2, h3);
            aL[0] = packbf(p0 - h0, p1 - h1); aL[1] = packbf(p2 - h2, p3 - h3);
            p0 = S[2 * u + 1][0]; p1 = S[2 * u + 1][1];
            p2 = S[2 * u + 1][2]; p3 = S[2 * u + 1][3];
            h0 = bf16rt(p0); h1 = bf16rt(p1); h2 = bf16rt(p2); h3 = bf16rt(p3);
            aH[2] = packbf(h0, h1);           aH[3] = packbf(h2, h3);
            aL[2] = packbf(p0 - h0, p1 - h1); aL[3] = packbf(p2 - h2, p3 - h3);
        }
        #pragma unroll
        for (int nt = 0; nt < 8; ++nt) {
            int off = (nt * 8 + g) * VSTRIDE + 8 * u + tq;
            uint32_t bh0 = sVh[off], bh1 = sVh[off + 4];
            uint32_t bl0 = sVl[off], bl1 = sVl[off + 4];
            mma16816(O[nt], aH, bh0, bh1);   // Ph*Vh
            mma16816(O[nt], aH, bl0, bl1);   // Ph*Vl
            mma16816(O[nt], aL, bh0, bh1);   // Pl*Vh
        }
    }

    float* oA = og + (size_t)rA * DD;
    float* oB = og + (size_t)rB * DD;
    #pragma unroll
    for (int nt = 0; nt < 8; ++nt) {
        *(float2*)&oA[8 * nt + 2 * tq] = make_float2(O[nt][0], O[nt][1]);
        *(float2*)&oB[8 * nt + 2 * tq] = make_float2(O[nt][2], O[nt][3]);
    }
}

extern "C" void kernel_launch(void* const* d_in, const int* in_sizes, int n_in,
                              void* d_out, int out_size)
{
    const float* q    = (const float*)d_in[0];
    const float* k    = (const float*)d_in[1];
    const float* v    = (const float*)d_in[2];
    const float* bias = (const float*)d_in[3];

    float* out  = (float*)d_out;
    float* attn = out + (size_t)HH * BSZ * LL * DD;

    const size_t smem = (size_t)(2 * 128 * KSTRIDE + 2 * 64 * VSTRIDE) * 4;  // 71680 B
    cudaFuncSetAttribute(attn_hmma_kernel,
                         cudaFuncAttributeMaxDynamicSharedMemorySize, (int)smem);

    dim3 grid(BSZ, HH);
    attn_hmma_kernel<<<grid, 256, smem>>>(q, k, v, bias, out, attn);
}

// round 5
// speedup vs baseline: 3.9479x; 1.0013x over previous
#include <cuda_runtime.h>
#include <cuda_bf16.h>
#include <cstdint>

// q,k,v: (H=8, B=256, L=128, D=64) fp32 ; pos_bias: (H,1,L,L)
// d_out = [ out (H,B,L,D) | attn (H,B,L,L) ]
#define HH 8
#define BSZ 256
#define LL 128
#define DD 64
#define STR 36   // u32 stride per tile row; 36 % 32 == 4 -> ldmatrix conflict-free

// u32-index offsets of the six 128x36 tiles
#define OQH 0
#define OQL (OQH + 128 * STR)
#define OKH (OQL + 128 * STR)
#define OKL (OKH + 128 * STR)
#define OVH (OKL + 128 * STR)
#define OVL (OVH + 128 * STR)
#define SMEM_U32 (OVL + 128 * STR)      // 27648 u32 = 110592 B

// pack two floats -> bf16x2 (first arg -> bits[15:0], second -> bits[31:16])
static __device__ __forceinline__ uint32_t packbf(float lo, float hi) {
    uint32_t r;
    asm("cvt.rn.bf16x2.f32 %0, %1, %2;" : "=r"(r) : "f"(hi), "f"(lo));
    return r;
}
static __device__ __forceinline__ float bf16rt(float x) {
    return __bfloat162float(__float2bfloat16_rn(x));
}
static __device__ __forceinline__ uint32_t smem_u32(const void* p) {
    uint32_t a;
    asm("{ .reg .u64 t; cvta.to.shared.u64 t, %1; cvt.u32.u64 %0, t; }" : "=r"(a) : "l"(p));
    return a;
}

// D += A * B  (m16n8k16, bf16 in, f32 accum)
static __device__ __forceinline__ void mma16816(float* d, const uint32_t* a,
                                                uint32_t b0, uint32_t b1) {
    asm volatile(
        "mma.sync.aligned.m16n8k16.row.col.f32.bf16.bf16.f32 "
        "{%0,%1,%2,%3}, {%4,%5,%6,%7}, {%8,%9}, {%0,%1,%2,%3};"
        : "+f"(d[0]), "+f"(d[1]), "+f"(d[2]), "+f"(d[3])
        : "r"(a[0]), "r"(a[1]), "r"(a[2]), "r"(a[3]), "r"(b0), "r"(b1));
}

#define LDSM_X4(r, a) \
    asm volatile("ldmatrix.sync.aligned.m8n8.x4.shared.b16 {%0,%1,%2,%3}, [%4];" \
        : "=r"((r)[0]), "=r"((r)[1]), "=r"((r)[2]), "=r"((r)[3]) : "r"(a))
#define LDSM_X4T(r, a) \
    asm volatile("ldmatrix.sync.aligned.m8n8.x4.trans.shared.b16 {%0,%1,%2,%3}, [%4];" \
        : "=r"((r)[0]), "=r"((r)[1]), "=r"((r)[2]), "=r"((r)[3]) : "r"(a))

static __device__ __forceinline__ void split4(float4 x, uint2& h, uint2& l) {
    float hx = bf16rt(x.x), hy = bf16rt(x.y), hz = bf16rt(x.z), hw = bf16rt(x.w);
    h = make_uint2(packbf(hx, hy), packbf(hz, hw));
    l = make_uint2(packbf(x.x - hx, x.y - hy), packbf(x.z - hz, x.w - hw));
}

__global__ __launch_bounds__(256, 2)
void attn_hmma2_kernel(const float* __restrict__ qg_,
                       const float* __restrict__ kg_,
                       const float* __restrict__ vg_,
                       const float* __restrict__ biasg,
                       float* __restrict__ outg,
                       float* __restrict__ attng)
{
    extern __shared__ uint32_t smu[];

    const int t = threadIdx.x;
    const int b = blockIdx.x;
    const int h = blockIdx.y;

    const size_t base  = (((size_t)h * BSZ + b) * LL) * DD;
    const size_t abase = (((size_t)h * BSZ + b) * LL) * LL;
    const float4* q4 = (const float4*)(qg_ + base);
    const float4* k4 = (const float4*)(kg_ + base);
    const float4* v4 = (const float4*)(vg_ + base);
    const float*  bg = biasg + (size_t)h * LL * LL;
    float*        ag = attng + abase;
    float*        og = outg + base;

    // ---- Stage Q, K, V as bf16 hi/lo, row-major, 36-u32 row stride ----
    #pragma unroll
    for (int it = 0; it < 8; ++it) {
        int idx = t + it * 256;               // 0..2047
        int row = idx >> 4, cg = idx & 15;
        int so = row * STR + 2 * cg;
        uint2 hh, ll;
        split4(q4[idx], hh, ll);
        *(uint2*)&smu[OQH + so] = hh; *(uint2*)&smu[OQL + so] = ll;
        split4(k4[idx], hh, ll);
        *(uint2*)&smu[OKH + so] = hh; *(uint2*)&smu[OKL + so] = ll;
        split4(v4[idx], hh, ll);
        *(uint2*)&smu[OVH + so] = hh; *(uint2*)&smu[OVL + so] = ll;
    }
    __syncthreads();

    const int w = t >> 5, lane = t & 31;
    const int g = lane >> 2, tq = lane & 3;
    const int i0 = w * 16;
    const int rA = i0 + g, rB = i0 + g + 8;

    // ---- per-lane ldmatrix base addresses (bytes) ----
    const uint32_t sb = smem_u32(smu);
    const int lr = lane & 7, lsel = lane >> 3;
    // A (Q): m0 rows i0..+7 klo | m1 rows i0+8..15 klo | m2 rows i0..7 khi | m3 +8 khi
    const uint32_t aQh = sb + 4u * (OQH + (uint32_t)((i0 + (lsel & 1) * 8 + lr) * STR
                                                     + (lsel >> 1) * 4));
    const uint32_t aQl = aQh + 4u * (OQL - OQH);
    // B (K): m0 Kh rows nt8.. b0 | m1 Kh b1 | m2 Kl b0 | m3 Kl b1
    const uint32_t aKb = sb + 4u * ((lsel >= 2 ? OKL : OKH)
                                    + (uint32_t)(lr * STR + (lsel & 1) * 4));
    // B (V, trans): m0 Vh rows j16u.. | m1 Vh +8 | m2 Vl | m3 Vl+8
    const uint32_t aVb = sb + 4u * ((lsel >= 2 ? OVL : OVH)
                                    + (uint32_t)(((lsel & 1) * 8 + lr) * STR));

    // =================== MMA 1: S = Q K^T (split precision) ===================
    float S[16][4];
    #pragma unroll
    for (int nt = 0; nt < 16; ++nt)
        S[nt][0] = S[nt][1] = S[nt][2] = S[nt][3] = 0.f;

    #pragma unroll
    for (int u = 0; u < 4; ++u) {             // k-chunks over d (4 x 16)
        uint32_t qh[4], ql[4];
        LDSM_X4(qh, aQh + 32u * u);           // +8 u32 per k-chunk
        LDSM_X4(ql, aQl + 32u * u);
        #pragma unroll
        for (int nt = 0; nt < 16; ++nt) {
            uint32_t bb[4];
            LDSM_X4(bb, aKb + (uint32_t)(nt * 8 * STR * 4) + 32u * u);
            mma16816(S[nt], qh, bb[0], bb[1]);   // qh*kh
            mma16816(S[nt], qh, bb[2], bb[3]);   // qh*kl
            mma16816(S[nt], ql, bb[0], bb[1]);   // ql*kh
        }
    }

    // =================== softmax (register/warp-local) ===================
    const float* bA = bg + (size_t)rA * LL;
    const float* bB = bg + (size_t)rB * LL;
    float mA = -1e30f, mB = -1e30f;
    #pragma unroll
    for (int nt = 0; nt < 16; ++nt) {
        float2 b0 = __ldg((const float2*)&bA[8 * nt + 2 * tq]);
        float2 b1 = __ldg((const float2*)&bB[8 * nt + 2 * tq]);
        S[nt][0] = fmaf(S[nt][0], 0.125f, b0.x);
        S[nt][1] = fmaf(S[nt][1], 0.125f, b0.y);
        S[nt][2] = fmaf(S[nt][2], 0.125f, b1.x);
        S[nt][3] = fmaf(S[nt][3], 0.125f, b1.y);
        mA = fmaxf(mA, fmaxf(S[nt][0], S[nt][1]));
        mB = fmaxf(mB, fmaxf(S[nt][2], S[nt][3]));
    }
    mA = fmaxf(mA, __shfl_xor_sync(0xffffffffu, mA, 1));
    mA = fmaxf(mA, __shfl_xor_sync(0xffffffffu, mA, 2));
    mB = fmaxf(mB, __shfl_xor_sync(0xffffffffu, mB, 1));
    mB = fmaxf(mB, __shfl_xor_sync(0xffffffffu, mB, 2));

    float sA = 0.f, sB = 0.f;
    #pragma unroll
    for (int nt = 0; nt < 16; ++nt) {
        S[nt][0] = __expf(S[nt][0] - mA); sA += S[nt][0];
        S[nt][1] = __expf(S[nt][1] - mA); sA += S[nt][1];
        S[nt][2] = __expf(S[nt][2] - mB); sB += S[nt][2];
        S[nt][3] = __expf(S[nt][3] - mB); sB += S[nt][3];
    }
    sA += __shfl_xor_sync(0xffffffffu, sA, 1);
    sA += __shfl_xor_sync(0xffffffffu, sA, 2);
    sB += __shfl_xor_sync(0xffffffffu, sB, 1);
    sB += __shfl_xor_sync(0xffffffffu, sB, 2);
    const float iA = 1.f / sA, iB = 1.f / sB;

    float* aA = ag + (size_t)rA * LL;
    float* aB = ag + (size_t)rB * LL;
    #pragma unroll
    for (int nt = 0; nt < 16; ++nt) {
        S[nt][0] *= iA; S[nt][1] *= iA; S[nt][2] *= iB; S[nt][3] *= iB;
        *(float2*)&aA[8 * nt + 2 * tq] = make_float2(S[nt][0], S[nt][1]);
        *(float2*)&aB[8 * nt + 2 * tq] = make_float2(S[nt][2], S[nt][3]);
    }

    // =================== MMA 2: O = P V (split precision) ===================
    float O[8][4];
    #pragma unroll
    for (int nt = 0; nt < 8; ++nt)
        O[nt][0] = O[nt][1] = O[nt][2] = O[nt][3] = 0.f;

    #pragma unroll
    for (int u = 0; u < 8; ++u) {             // k-chunks over j (8 x 16)
        uint32_t aH[4], aL[4];
        {
            float p0 = S[2 * u][0], p1 = S[2 * u][1];
            float p2 = S[2 * u][2], p3 = S[2 * u][3];
            float h0 = bf16rt(p0), h1 = bf16rt(p1), h2 = bf16rt(p2), h3 = bf16rt(p3);
            aH[0] = packbf(h0, h1);           aH[1] = packbf(h2, h3);
            aL[0] = packbf(p0 - h0, p1 - h1); aL[1] = packbf(p2 - h2, p3 - h3);
            p0 = S[2 * u + 1][0]; p1 = S[2 * u + 1][1];
            p2 = S[2 * u + 1][2]; p3 = S[2 * u + 1][3];
            h0 = bf16rt(p0); h1 = bf16rt(p1); h2 = bf16rt(p2); h3 = bf16rt(p3);
            aH[2] = packbf(h0, h1);           aH[3] = packbf(h2, h3);
            aL[2] = packbf(p0 - h0, p1 - h1); aL[3] = packbf(p2 - h2, p3 - h3);
        }
        #pragma unroll
        for (int nt = 0; nt < 8; ++nt) {
            uint32_t bb[4];
            LDSM_X4T(bb, aVb + (uint32_t)(u * 16 * STR * 4) + (uint32_t)(nt * 16));
            mma16816(O[nt], aH, bb[0], bb[1]);   // Ph*Vh
            mma16816(O[nt], aH, bb[2], bb[3]);   // Ph*Vl
            mma16816(O[nt], aL, bb[0], bb[1]);   // Pl*Vh
        }
    }

    float* oA = og + (size_t)rA * DD;
    float* oB = og + (size_t)rB * DD;
    #pragma unroll
    for (int nt = 0; nt < 8; ++nt) {
        *(float2*)&oA[8 * nt + 2 * tq] = make_float2(O[nt][0], O[nt][1]);
        *(float2*)&oB[8 * nt + 2 * tq] = make_float2(O[nt][2], O[nt][3]);
    }
}

extern "C" void kernel_launch(void* const* d_in, const int* in_sizes, int n_in,
                              void* d_out, int out_size)
{
    const float* q    = (const float*)d_in[0];
    const float* k    = (const float*)d_in[1];
    const float* v    = (const float*)d_in[2];
    const float* bias = (const float*)d_in[3];

    float* out  = (float*)d_out;
    float* attn = out + (size_t)HH * BSZ * LL * DD;

    const size_t smem = (size_t)SMEM_U32 * 4;   // 110592 B
    cudaFuncSetAttribute(attn_hmma2_kernel,
                         cudaFuncAttributeMaxDynamicSharedMemorySize, (int)smem);

    dim3 grid(BSZ, HH);
    attn_hmma2_kernel<<<grid, 256, smem>>>(q, k, v, bias, out, attn);
}